// round 7
// baseline (speedup 1.0000x reference)
#include <cuda_runtime.h>
#include <cuda_bf16.h>

// ESN recurrence: x_t = tanh(w_in*u_t + W @ x_{t-1}); out[t-washout] = sum_r w_out[r]*x_t[r]
// Strategy: W register-resident across a 128-CTA persistent kernel (single wave,
// hand-rolled grid barrier per step), packed f32x2 FMAs, x exchanged via L2.

#define H          2048
#define T          8192
#define NCTA       128
#define NTHR       512
#define ROWS_CTA   16     // H / NCTA
// Per warp: 4 rows x 512 cols. 16 warps = 4 row-groups x 4 col-groups.
// Per lane: 4 rows x 16 cols (as 4 float4 column chunks), 64 W floats in regs.

__device__ float    g_x[2 * H];           // double-buffered state
__device__ float    g_part[NCTA * T];     // per-CTA partial output sums, [b][t-washout], stride T
__device__ unsigned g_counter;            // monotone step-arrival counter

// ---------- helpers ----------
__device__ __forceinline__ unsigned ld_acq(const unsigned* p) {
    unsigned v;
    asm volatile("ld.acquire.gpu.global.u32 %0, [%1];" : "=r"(v) : "l"(p) : "memory");
    return v;
}
__device__ __forceinline__ unsigned long long pack2(float a, float b) {
    unsigned long long r;
    asm("mov.b64 %0, {%1, %2};" : "=l"(r) : "f"(a), "f"(b));
    return r;
}
__device__ __forceinline__ void unpack2(float& a, float& b, unsigned long long v) {
    asm("mov.b64 {%0, %1}, %2;" : "=f"(a), "=f"(b) : "l"(v));
}
__device__ __forceinline__ unsigned long long fma2(unsigned long long a,
                                                   unsigned long long b,
                                                   unsigned long long c) {
    unsigned long long d;
    asm("fma.rn.f32x2 %0, %1, %2, %3;" : "=l"(d) : "l"(a), "l"(b), "l"(c));
    return d;
}
__device__ __forceinline__ float4 ldcv_f4(const float4* p) {
    float4 v;
    asm volatile("ld.global.cv.v4.f32 {%0,%1,%2,%3}, [%4];"
                 : "=f"(v.x), "=f"(v.y), "=f"(v.z), "=f"(v.w) : "l"(p) : "memory");
    return v;
}

// ---------- init: zero state buffer 0 and the barrier counter ----------
__global__ void esn_init_kernel() {
    int i = blockIdx.x * blockDim.x + threadIdx.x;
    if (i < H) g_x[i] = 0.0f;
    if (i == 0) g_counter = 0u;
}

// ---------- main persistent kernel ----------
__global__ void __launch_bounds__(NTHR, 1)
esn_main_kernel(const float* __restrict__ u,
                const float* __restrict__ w_res,
                const float* __restrict__ w_in,
                const float* __restrict__ w_out,
                const int*   __restrict__ washout_p)
{
    __shared__ float4 sx[H / 4];          // 8 KB: current state vector
    __shared__ float  spart[16][128];     // 8 KB: per-lane row partials
    __shared__ float  srow[16];           // weighted new-state rows for output sum

    const int tid  = threadIdx.x;
    const int lane = tid & 31;
    const int w    = tid >> 5;            // warp 0..15
    const int b    = blockIdx.x;
    const int rg   = w >> 2;              // row-group 0..3
    const int cg   = w & 3;               // col-group 0..3
    const int row0 = b * ROWS_CTA + rg * 4;

    // Preload this lane's 4x16 W tile into registers as f32x2 pairs.
    unsigned long long wp[4][4][2];
#pragma unroll
    for (int r = 0; r < 4; ++r) {
#pragma unroll
        for (int j = 0; j < 4; ++j) {
            const float4* p = (const float4*)(w_res + (size_t)(row0 + r) * H
                                              + cg * 512 + j * 128 + 4 * lane);
            float4 wv = __ldg(p);
            wp[r][j][0] = pack2(wv.x, wv.y);
            wp[r][j][1] = pack2(wv.z, wv.w);
        }
    }

    // Reduce-phase constants: warp w owns local row w.
    const int myrow = b * ROWS_CTA + w;
    float win_r = 0.0f, wo_r = 0.0f;
    if (lane == 0) {
        win_r = __ldg(w_in + myrow);
        wo_r  = __ldg(w_out + myrow);
    }
    const int washout = __ldg(washout_p);

    for (int t = 0; t < T; ++t) {
        // ---- grid barrier: wait until every CTA finished step t-1 ----
        if (tid == 0 && t > 0) {
            const unsigned tgt = (unsigned)t * NCTA;
            while (ld_acq(&g_counter) < tgt) { }
        }
        __syncthreads();

        // ---- stage x_t into shared (L1-bypassing loads; other SMs wrote it) ----
        const float4* xsrc = (const float4*)(g_x + (t & 1) * H);
        sx[tid] = ldcv_f4(xsrc + tid);

        float u_t = 0.0f;
        if (lane == 0) u_t = __ldg(u + t);   // overlap with barrier
        __syncthreads();

        // ---- matvec partial: 4 rows x 16 cols per lane, packed FMA ----
        unsigned long long xp[4][2];
#pragma unroll
        for (int j = 0; j < 4; ++j) {
            float4 v = sx[cg * 128 + j * 32 + lane];
            xp[j][0] = pack2(v.x, v.y);
            xp[j][1] = pack2(v.z, v.w);
        }
        unsigned long long acc[4] = {0ull, 0ull, 0ull, 0ull};
#pragma unroll
        for (int r = 0; r < 4; ++r) {
#pragma unroll
            for (int j = 0; j < 4; ++j) {
                acc[r] = fma2(wp[r][j][0], xp[j][0], acc[r]);
                acc[r] = fma2(wp[r][j][1], xp[j][1], acc[r]);
            }
        }
#pragma unroll
        for (int r = 0; r < 4; ++r) {
            float lo, hi;
            unpack2(lo, hi, acc[r]);
            spart[rg * 4 + r][cg * 32 + lane] = lo + hi;
        }
        __syncthreads();

        // ---- reduce: warp w sums local row w (128 partials) ----
        float v = spart[w][lane] + spart[w][lane + 32]
                + spart[w][lane + 64] + spart[w][lane + 96];
        v += __shfl_xor_sync(0xffffffffu, v, 16);
        v += __shfl_xor_sync(0xffffffffu, v, 8);
        v += __shfl_xor_sync(0xffffffffu, v, 4);
        v += __shfl_xor_sync(0xffffffffu, v, 2);
        v += __shfl_xor_sync(0xffffffffu, v, 1);

        if (lane == 0) {
            float xn = tanhf(fmaf(win_r, u_t, v));
            g_x[((t + 1) & 1) * H + myrow] = xn;   // publish new state row
            srow[w] = wo_r * xn;                   // weighted for output
        }
        __syncthreads();

        // ---- single arrival per CTA (release), plus output partial ----
        if (tid == 0) {
            if (t >= washout) {
                float s = 0.0f;
#pragma unroll
                for (int k = 0; k < 16; ++k) s += srow[k];
                g_part[(size_t)b * T + (t - washout)] = s;
            }
            __threadfence();                 // order x/state writes before arrival
            atomicAdd(&g_counter, 1u);
        }
    }
}

// ---------- final reduce: out[j] = sum_b g_part[b][j] ----------
__global__ void esn_reduce_kernel(float* __restrict__ out, int n) {
    int j = blockIdx.x * blockDim.x + threadIdx.x;
    if (j < n) {
        float s = 0.0f;
#pragma unroll 16
        for (int bb = 0; bb < NCTA; ++bb)
            s += g_part[(size_t)bb * T + j];
        out[j] = s;
    }
}

extern "C" void kernel_launch(void* const* d_in, const int* in_sizes, int n_in,
                              void* d_out, int out_size) {
    const float* u       = (const float*)d_in[0];
    const float* w_res   = (const float*)d_in[1];
    const float* w_in    = (const float*)d_in[2];
    const float* w_out   = (const float*)d_in[3];
    // d_in[4]: w_out_mask == arange(H) (identity gather) — folded out.
    const int*   washout = (const int*)d_in[5];

    esn_init_kernel<<<(H + 255) / 256, 256>>>();
    esn_main_kernel<<<NCTA, NTHR>>>(u, w_res, w_in, w_out, washout);
    esn_reduce_kernel<<<(out_size + 255) / 256, 256>>>((float*)d_out, out_size);
}

// round 9
// speedup vs baseline: 1.1183x; 1.1183x over previous
#include <cuda_runtime.h>
#include <cuda_bf16.h>

// ESN: x_{t+1} = tanh(w_in*u_t + W @ x_t); out[t-washout] = w_out . x_{t+1}
// Barrier-free dataflow: state elements published as (value, step-tag) 8-byte
// atomic pairs; consumers spin on tags with predicated .cv retries. Double
// buffering is sufficient: a producer can only reach step t+2's writes after
// it has fully read step-t state, and it reads ALL of x_t before publishing
// any of x_{t+1}.
// Reduction: butterfly-with-register-packing (16 rows x 32 lanes in 31 SHFLs),
// since redux.sync.add.f32 is NOT in the sm_103 ISA.

#define HN   2048
#define TN   8192
#define NCTA 128     // 16 rows per CTA; single wave on 148 SMs (co-residency guaranteed)
#define NTHR 512     // 16 warps; warp w: 16 rows x cols [w*128, w*128+128)

__device__ float2 g_xs[2][HN];                    // (value, tag bits), double buffered
__device__ float  g_hist[(size_t)TN * HN];        // 64 MB state history for deferred readout

// ---------- helpers ----------
__device__ __forceinline__ unsigned long long pack2(float a, float b) {
    unsigned long long r;
    asm("mov.b64 %0, {%1, %2};" : "=l"(r) : "f"(a), "f"(b));
    return r;
}
__device__ __forceinline__ void unpack2(float& a, float& b, unsigned long long v) {
    asm("mov.b64 {%0, %1}, %2;" : "=f"(a), "=f"(b) : "l"(v));
}
__device__ __forceinline__ unsigned long long fma2(unsigned long long a,
                                                   unsigned long long b,
                                                   unsigned long long c) {
    unsigned long long d;
    asm("fma.rn.f32x2 %0, %1, %2, %3;" : "=l"(d) : "l"(a), "l"(b), "l"(c));
    return d;
}
__device__ __forceinline__ float4 ldcv_f4(const float4* p) {
    float4 v;
    asm volatile("ld.global.cv.v4.f32 {%0,%1,%2,%3}, [%4];"
                 : "=f"(v.x), "=f"(v.y), "=f"(v.z), "=f"(v.w) : "l"(p) : "memory");
    return v;
}
__device__ __forceinline__ void stcg_f2(float2* p, float2 v) {
    asm volatile("st.global.cg.v2.f32 [%0], {%1, %2};"
                 :: "l"(p), "f"(v.x), "f"(v.y) : "memory");
}
__device__ __forceinline__ float tanh_fast(float x) {
    float ax = fabsf(x);
    float e  = __expf(-2.0f * ax);                 // MUFU.EX2 path
    float r  = __fdividef(1.0f - e, 1.0f + e);     // MUFU.RCP path, numerically stable
    return copysignf(r, x);
}

// 16 row-partials per lane -> lane L returns full warp-sum of row ((L>>1)&15).
// After v[r] += shfl_xor(v[r], m), BOTH partner lanes hold the sum, so the
// folded register is valid everywhere and packing is a pure SEL.
__device__ __forceinline__ float reduce_rows16(float v[16], int lane) {
#pragma unroll
    for (int r = 0; r < 16; ++r) v[r] += __shfl_xor_sync(0xffffffffu, v[r], 16);
    float w8[8];
#pragma unroll
    for (int r = 0; r < 8; ++r) w8[r] = (lane & 16) ? v[r + 8] : v[r];
#pragma unroll
    for (int r = 0; r < 8; ++r) w8[r] += __shfl_xor_sync(0xffffffffu, w8[r], 8);
    float w4[4];
#pragma unroll
    for (int r = 0; r < 4; ++r) w4[r] = (lane & 8) ? w8[r + 4] : w8[r];
#pragma unroll
    for (int r = 0; r < 4; ++r) w4[r] += __shfl_xor_sync(0xffffffffu, w4[r], 4);
    float w2[2];
    w2[0] = (lane & 4) ? w4[2] : w4[0];
    w2[1] = (lane & 4) ? w4[3] : w4[1];
    w2[0] += __shfl_xor_sync(0xffffffffu, w2[0], 2);
    w2[1] += __shfl_xor_sync(0xffffffffu, w2[1], 2);
    float z = (lane & 2) ? w2[1] : w2[0];
    z += __shfl_xor_sync(0xffffffffu, z, 1);
    return z;
}

// ---------- init: tag buffer 0 as step 0 (x_0 = 0), invalidate buffer 1 ----------
__global__ void esn_init_kernel() {
    int i = blockIdx.x * blockDim.x + threadIdx.x;
    if (i < HN) {
        g_xs[0][i] = make_float2(0.0f, __int_as_float(0));
        g_xs[1][i] = make_float2(0.0f, __int_as_float(-1));
    }
}

// ---------- main persistent recurrence kernel ----------
__global__ void __launch_bounds__(NTHR, 1)
esn_main_kernel(const float* __restrict__ u,
                const float* __restrict__ w_res,
                const float* __restrict__ w_in)
{
    __shared__ float spart[2][16][17];   // [parity][row][warp], padded

    const int tid   = threadIdx.x;
    const int lane  = tid & 31;
    const int w     = tid >> 5;          // warp 0..15
    const int b     = blockIdx.x;
    const int myrow = b * 16 + w;        // row this warp finalizes/publishes

    // Preload W tile: warp w covers rows [b*16, b*16+16) x cols [w*128, w*128+128).
    // Lane's 4 columns: {w*128+2l, +1, w*128+64+2l, +1} (coalesced float2 loads).
    unsigned long long wp[16][2];
#pragma unroll
    for (int r = 0; r < 16; ++r) {
        const float2* p0 = (const float2*)(w_res + (size_t)(b * 16 + r) * HN
                                           + w * 128 + 2 * lane);
        float2 a = __ldg(p0);
        float2 c = __ldg(p0 + 32);       // +64 columns
        wp[r][0] = pack2(a.x, a.y);
        wp[r][1] = pack2(c.x, c.y);
    }
    const float win_r = __ldg(w_in + myrow);

    for (int t = 0; t < TN; ++t) {
        float u_t = __ldg(u + t);        // L1-resident sequential 4B

        // ---- spin-load this lane's 2 pair-quads of x_t (tags == t) ----
        const float4* src = (const float4*)(&g_xs[t & 1][0]) + w * 64 + lane;
        float4 v0, v1;
        bool d0 = false, d1 = false;
        do {
            if (!d0) { v0 = ldcv_f4(src);
                       d0 = (__float_as_int(v0.y) == t) && (__float_as_int(v0.w) == t); }
            if (!d1) { v1 = ldcv_f4(src + 32);
                       d1 = (__float_as_int(v1.y) == t) && (__float_as_int(v1.w) == t); }
        } while (__any_sync(0xffffffffu, (!d0) || (!d1)));

        const unsigned long long x01 = pack2(v0.x, v0.z);
        const unsigned long long x23 = pack2(v1.x, v1.z);

        // ---- 16 rows x 4 cols per lane: 2 chained f32x2 FMAs per row ----
        float part[16];
#pragma unroll
        for (int r = 0; r < 16; ++r) {
            unsigned long long a = fma2(wp[r][0], x01, 0ull);
            a = fma2(wp[r][1], x23, a);
            float lo, hi;
            unpack2(lo, hi, a);
            part[r] = lo + hi;
        }

        // ---- intra-warp: 31-SHFL packed butterfly; lane 2r holds row r's sum ----
        float z = reduce_rows16(part, lane);
        if ((lane & 1) == 0) spart[t & 1][lane >> 1][w] = z;
        __syncthreads();   // spart[parity] ready (the ONLY block barrier per step)

        // ---- cross-warp: warp w reduces its row across 16 warps, publishes ----
        float val = (lane < 16) ? spart[t & 1][w][lane] : 0.0f;
        val += __shfl_xor_sync(0xffffffffu, val, 8);
        val += __shfl_xor_sync(0xffffffffu, val, 4);
        val += __shfl_xor_sync(0xffffffffu, val, 2);
        val += __shfl_xor_sync(0xffffffffu, val, 1);
        if (lane == 0) {
            float xn = tanh_fast(fmaf(win_r, u_t, val));
            float2 pr;
            pr.x = xn;
            pr.y = __int_as_float(t + 1);
            stcg_f2(&g_xs[(t + 1) & 1][myrow], pr);   // 8B atomic publish: value+tag
            g_hist[(size_t)t * HN + myrow] = xn;      // deferred-readout history
        }
    }
}

// ---------- deferred readout: out[j] = w_out . hist[washout + j] ----------
__global__ void esn_out_kernel(const float* __restrict__ w_out,
                               const int*   __restrict__ washout_p,
                               float* __restrict__ out, int n)
{
    int j = blockIdx.x;
    if (j >= n) return;
    const int washout = *washout_p;
    const float* row = g_hist + (size_t)(j + washout) * HN;

    float s = 0.0f;
#pragma unroll 4
    for (int r = threadIdx.x; r < HN; r += 256)
        s += row[r] * __ldg(w_out + r);

    s += __shfl_xor_sync(0xffffffffu, s, 16);
    s += __shfl_xor_sync(0xffffffffu, s, 8);
    s += __shfl_xor_sync(0xffffffffu, s, 4);
    s += __shfl_xor_sync(0xffffffffu, s, 2);
    s += __shfl_xor_sync(0xffffffffu, s, 1);

    __shared__ float sb[8];
    if ((threadIdx.x & 31) == 0) sb[threadIdx.x >> 5] = s;
    __syncthreads();
    if (threadIdx.x < 8) {
        float v = sb[threadIdx.x];
        v += __shfl_xor_sync(0x000000ffu, v, 4);
        v += __shfl_xor_sync(0x000000ffu, v, 2);
        v += __shfl_xor_sync(0x000000ffu, v, 1);
        if (threadIdx.x == 0) out[j] = v;
    }
}

extern "C" void kernel_launch(void* const* d_in, const int* in_sizes, int n_in,
                              void* d_out, int out_size) {
    const float* u       = (const float*)d_in[0];
    const float* w_res   = (const float*)d_in[1];
    const float* w_in    = (const float*)d_in[2];
    const float* w_out   = (const float*)d_in[3];
    // d_in[4]: w_out_mask == arange(H) (identity gather) — folded out.
    const int*   washout = (const int*)d_in[5];

    esn_init_kernel<<<(HN + 255) / 256, 256>>>();
    esn_main_kernel<<<NCTA, NTHR>>>(u, w_res, w_in);
    esn_out_kernel<<<out_size, 256>>>(w_out, washout, (float*)d_out, out_size);
}

// round 10
// speedup vs baseline: 1.2122x; 1.0840x over previous
#include <cuda_runtime.h>
#include <cuda_bf16.h>

// ESN: x_{t+1} = tanh(w_in*u_t + W @ x_t); out[t-washout] = w_out . x_{t+1}
// Barrier-free dataflow: state elements published as (value, step-tag) 8-byte
// atomic pairs via st.cg; consumers spin with ld.cg (L2 is the coherence
// point — .cv was forcing DRAM-class refetches, R9's bottleneck theory).
// Double buffering is sufficient: a producer reads ALL of x_t before
// publishing any of x_{t+1}, so tags t and t+2 never coexist unconsumed.

#define HN   2048
#define TN   8192
#define NCTA 128     // 16 rows per CTA; single wave on 148 SMs
#define NTHR 512     // 16 warps; warp w: 16 rows x cols [w*128, w*128+128)

__device__ float2 g_xs[2][HN];                    // (value, tag bits), double buffered
__device__ float  g_hist[(size_t)TN * HN];        // 64 MB state history for deferred readout

// ---------- helpers ----------
__device__ __forceinline__ unsigned long long pack2(float a, float b) {
    unsigned long long r;
    asm("mov.b64 %0, {%1, %2};" : "=l"(r) : "f"(a), "f"(b));
    return r;
}
__device__ __forceinline__ void unpack2(float& a, float& b, unsigned long long v) {
    asm("mov.b64 {%0, %1}, %2;" : "=f"(a), "=f"(b) : "l"(v));
}
__device__ __forceinline__ unsigned long long fma2(unsigned long long a,
                                                   unsigned long long b,
                                                   unsigned long long c) {
    unsigned long long d;
    asm("fma.rn.f32x2 %0, %1, %2, %3;" : "=l"(d) : "l"(a), "l"(b), "l"(c));
    return d;
}
// Spin load: bypass L1, hit L2 (coherence point). NOT .cv — that refetches
// past L2 and was DRAM-bound.
__device__ __forceinline__ float4 ldcg_f4(const float4* p) {
    float4 v;
    asm volatile("ld.global.cg.v4.f32 {%0,%1,%2,%3}, [%4];"
                 : "=f"(v.x), "=f"(v.y), "=f"(v.z), "=f"(v.w) : "l"(p) : "memory");
    return v;
}
__device__ __forceinline__ void stcg_f2(float2* p, float2 v) {
    asm volatile("st.global.cg.v2.f32 [%0], {%1, %2};"
                 :: "l"(p), "f"(v.x), "f"(v.y) : "memory");
}
__device__ __forceinline__ float tanh_hw(float x) {
    float r;
    asm("tanh.approx.f32 %0, %1;" : "=f"(r) : "f"(x));
    return r;
}

// 16 row-partials per lane -> lane L returns full warp-sum of row ((L>>1)&15).
__device__ __forceinline__ float reduce_rows16(float v[16], int lane) {
#pragma unroll
    for (int r = 0; r < 16; ++r) v[r] += __shfl_xor_sync(0xffffffffu, v[r], 16);
    float w8[8];
#pragma unroll
    for (int r = 0; r < 8; ++r) w8[r] = (lane & 16) ? v[r + 8] : v[r];
#pragma unroll
    for (int r = 0; r < 8; ++r) w8[r] += __shfl_xor_sync(0xffffffffu, w8[r], 8);
    float w4[4];
#pragma unroll
    for (int r = 0; r < 4; ++r) w4[r] = (lane & 8) ? w8[r + 4] : w8[r];
#pragma unroll
    for (int r = 0; r < 4; ++r) w4[r] += __shfl_xor_sync(0xffffffffu, w4[r], 4);
    float w2[2];
    w2[0] = (lane & 4) ? w4[2] : w4[0];
    w2[1] = (lane & 4) ? w4[3] : w4[1];
    w2[0] += __shfl_xor_sync(0xffffffffu, w2[0], 2);
    w2[1] += __shfl_xor_sync(0xffffffffu, w2[1], 2);
    float z = (lane & 2) ? w2[1] : w2[0];
    z += __shfl_xor_sync(0xffffffffu, z, 1);
    return z;
}

// ---------- init: tag buffer 0 as step 0 (x_0 = 0), invalidate buffer 1 ----------
__global__ void esn_init_kernel() {
    int i = blockIdx.x * blockDim.x + threadIdx.x;
    if (i < HN) {
        g_xs[0][i] = make_float2(0.0f, __int_as_float(0));
        g_xs[1][i] = make_float2(0.0f, __int_as_float(-1));
    }
}

// ---------- profiling-slot pads (no-ops) ----------
__global__ void esn_pad1_kernel() {}
__global__ void esn_pad2_kernel() {}

// ---------- main persistent recurrence kernel ----------
__global__ void __launch_bounds__(NTHR, 1)
esn_main_kernel(const float* __restrict__ u,
                const float* __restrict__ w_res,
                const float* __restrict__ w_in)
{
    __shared__ float spart[2][16][17];   // [parity][row][warp], padded

    const int tid   = threadIdx.x;
    const int lane  = tid & 31;
    const int w     = tid >> 5;          // warp 0..15
    const int b     = blockIdx.x;
    const int myrow = b * 16 + w;        // row this warp finalizes/publishes

    // Preload W tile: warp w covers rows [b*16, b*16+16) x cols [w*128, +128).
    // Lane's 4 columns: {w*128+2l, +1, w*128+64+2l, +1} (coalesced float2 loads).
    unsigned long long wp[16][2];
#pragma unroll
    for (int r = 0; r < 16; ++r) {
        const float2* p0 = (const float2*)(w_res + (size_t)(b * 16 + r) * HN
                                           + w * 128 + 2 * lane);
        float2 a = __ldg(p0);
        float2 c = __ldg(p0 + 32);       // +64 columns
        wp[r][0] = pack2(a.x, a.y);
        wp[r][1] = pack2(c.x, c.y);
    }
    const float win_r = __ldg(w_in + myrow);

    for (int t = 0; t < TN; ++t) {
        float u_t = __ldg(u + t);        // L1-resident sequential 4B

        // ---- spin-load this lane's 2 pair-quads of x_t (tags == t) ----
        const float4* src = (const float4*)(&g_xs[t & 1][0]) + w * 64 + lane;
        float4 v0, v1;
        bool d0 = false, d1 = false;
#pragma unroll 1
        while (true) {
            if (!d0) { v0 = ldcg_f4(src);
                       d0 = (__float_as_int(v0.y) == t) && (__float_as_int(v0.w) == t); }
            if (!d1) { v1 = ldcg_f4(src + 32);
                       d1 = (__float_as_int(v1.y) == t) && (__float_as_int(v1.w) == t); }
            if (!__any_sync(0xffffffffu, (!d0) || (!d1))) break;
            __nanosleep(32);             // convergent backoff: tame L2 poll storm
        }

        const unsigned long long x01 = pack2(v0.x, v0.z);
        const unsigned long long x23 = pack2(v1.x, v1.z);

        // ---- 16 rows x 4 cols per lane: 2 chained f32x2 FMAs per row ----
        float part[16];
#pragma unroll
        for (int r = 0; r < 16; ++r) {
            unsigned long long a = fma2(wp[r][0], x01, 0ull);
            a = fma2(wp[r][1], x23, a);
            float lo, hi;
            unpack2(lo, hi, a);
            part[r] = lo + hi;
        }

        // ---- intra-warp: 31-SHFL packed butterfly; lane 2r holds row r ----
        float z = reduce_rows16(part, lane);
        if ((lane & 1) == 0) spart[t & 1][lane >> 1][w] = z;
        __syncthreads();   // the ONLY block barrier per step

        // ---- cross-warp: warp w reduces its row across 16 warps, publishes ----
        float val = (lane < 16) ? spart[t & 1][w][lane] : 0.0f;
        val += __shfl_xor_sync(0xffffffffu, val, 8);
        val += __shfl_xor_sync(0xffffffffu, val, 4);
        val += __shfl_xor_sync(0xffffffffu, val, 2);
        val += __shfl_xor_sync(0xffffffffu, val, 1);
        if (lane == 0) {
            float xn = tanh_hw(fmaf(win_r, u_t, val));
            float2 pr;
            pr.x = xn;
            pr.y = __int_as_float(t + 1);
            stcg_f2(&g_xs[(t + 1) & 1][myrow], pr);   // 8B atomic publish: value+tag
            g_hist[(size_t)t * HN + myrow] = xn;      // deferred-readout history
        }
    }
}

// ---------- deferred readout: out[j] = w_out . hist[washout + j] ----------
__global__ void esn_out_kernel(const float* __restrict__ w_out,
                               const int*   __restrict__ washout_p,
                               float* __restrict__ out, int n)
{
    int j = blockIdx.x;
    if (j >= n) return;
    const int washout = *washout_p;
    const float* row = g_hist + (size_t)(j + washout) * HN;

    float s = 0.0f;
#pragma unroll 4
    for (int r = threadIdx.x; r < HN; r += 256)
        s += row[r] * __ldg(w_out + r);

    s += __shfl_xor_sync(0xffffffffu, s, 16);
    s += __shfl_xor_sync(0xffffffffu, s, 8);
    s += __shfl_xor_sync(0xffffffffu, s, 4);
    s += __shfl_xor_sync(0xffffffffu, s, 2);
    s += __shfl_xor_sync(0xffffffffu, s, 1);

    __shared__ float sb[8];
    if ((threadIdx.x & 31) == 0) sb[threadIdx.x >> 5] = s;
    __syncthreads();
    if (threadIdx.x < 8) {
        float v = sb[threadIdx.x];
        v += __shfl_xor_sync(0x000000ffu, v, 4);
        v += __shfl_xor_sync(0x000000ffu, v, 2);
        v += __shfl_xor_sync(0x000000ffu, v, 1);
        if (threadIdx.x == 0) out[j] = v;
    }
}

extern "C" void kernel_launch(void* const* d_in, const int* in_sizes, int n_in,
                              void* d_out, int out_size) {
    const float* u       = (const float*)d_in[0];
    const float* w_res   = (const float*)d_in[1];
    const float* w_in    = (const float*)d_in[2];
    const float* w_out   = (const float*)d_in[3];
    // d_in[4]: w_out_mask == arange(H) (identity gather) — folded out.
    const int*   washout = (const int*)d_in[5];

    esn_init_kernel<<<(HN + 255) / 256, 256>>>();
    esn_pad1_kernel<<<1, 32>>>();   // profiling-slot pads so ncu -s 5 -c 1
    esn_pad2_kernel<<<1, 32>>>();   // lands on esn_main_kernel next capture
    esn_main_kernel<<<NCTA, NTHR>>>(u, w_res, w_in);
    esn_out_kernel<<<out_size, 256>>>(w_out, washout, (float*)d_out, out_size);
}